// round 3
// baseline (speedup 1.0000x reference)
#include <cuda_runtime.h>
#include <math.h>

#define B_ 8
#define N_ 256
#define D_ 512
#define H_ 16
#define K_ 4
#define DK_ 32
#define FFN_ 2048
#define BN_ 2048   // B*N
#define KD_ 2048   // K*D

// ------------------- scratch (static device allocations) -------------------
__device__ float g_q[BN_ * D_];
__device__ float g_k[BN_ * D_];
__device__ float g_v[BN_ * D_];
__device__ float g_msg[BN_ * KD_];
__device__ float g_t1[BN_ * D_];
__device__ float g_t2[BN_ * D_];
__device__ float g_y[BN_ * D_];
__device__ float g_t3[BN_ * FFN_];
__device__ float g_t4[BN_ * D_];

// ------------------- generic fp32 tiled GEMM: C = act(A@W + bias) ----------
// A [M, Kc] row-major, W [Kc, Nc] row-major, C [M, Nc].
// Block tile 128(M) x 64(N) x 16(K). 256 threads, 8x4 micro-tile.
// All dims are exact multiples (M=2048, Nc in {512,2048}, Kc in {512,2048}).
template <int ACT>
__global__ __launch_bounds__(256) void gemm_kernel(
    const float* __restrict__ A, const float* __restrict__ W,
    const float* __restrict__ bias, float* __restrict__ C,
    int M, int Nc, int Kc)
{
    __shared__ float As[128 * 17];
    __shared__ float Bs[16 * 64];

    int tid = threadIdx.x;
    int tx = tid & 15;
    int ty = tid >> 4;
    int rowBase = blockIdx.y * 128;
    int colBase = blockIdx.x * 64;

    float acc[8][4];
#pragma unroll
    for (int i = 0; i < 8; i++)
#pragma unroll
        for (int j = 0; j < 4; j++) acc[i][j] = 0.f;

    for (int k0 = 0; k0 < Kc; k0 += 16) {
        // A tile: 128x16 = 2048 floats = 512 float4
#pragma unroll
        for (int l = 0; l < 2; l++) {
            int e4 = tid + l * 256;
            int r = e4 >> 2;
            int c4 = e4 & 3;
            float4 av = *(const float4*)&A[(size_t)(rowBase + r) * Kc + k0 + c4 * 4];
            As[r * 17 + c4 * 4 + 0] = av.x;
            As[r * 17 + c4 * 4 + 1] = av.y;
            As[r * 17 + c4 * 4 + 2] = av.z;
            As[r * 17 + c4 * 4 + 3] = av.w;
        }
        // B tile: 16x64 = 1024 floats = 256 float4
        {
            int r = tid >> 4;
            int c4 = tid & 15;
            float4 wv = *(const float4*)&W[(size_t)(k0 + r) * Nc + colBase + c4 * 4];
            *(float4*)&Bs[r * 64 + c4 * 4] = wv;
        }
        __syncthreads();

#pragma unroll
        for (int kk = 0; kk < 16; kk++) {
            float4 bv = *(const float4*)&Bs[kk * 64 + tx * 4];
#pragma unroll
            for (int i = 0; i < 8; i++) {
                float a = As[(ty * 8 + i) * 17 + kk];
                acc[i][0] += a * bv.x;
                acc[i][1] += a * bv.y;
                acc[i][2] += a * bv.z;
                acc[i][3] += a * bv.w;
            }
        }
        __syncthreads();
    }

#pragma unroll
    for (int i = 0; i < 8; i++) {
        int r = rowBase + ty * 8 + i;
#pragma unroll
        for (int j = 0; j < 4; j++) {
            int c = colBase + tx * 4 + j;
            float v = acc[i][j] + bias[c];
            if (ACT == 1) {                       // SiLU
                v = v / (1.f + __expf(-v));
            } else if (ACT == 2) {                // exact GELU
                v = 0.5f * v * (1.f + erff(v * 0.70710678118654752f));
            }
            C[(size_t)r * Nc + c] = v;
        }
    }
}

// ------------------- fused multi-scale attention ---------------------------
// One block per (b,h). K/V tiles resident in smem (padded rows, 33 floats).
// Each warp owns one query at a time; all 4 distance scales are softmaxed,
// p stored as float4-per-key, then a single V pass accumulates all 4 scales.
// Output scattered directly into the faithful torch-reshape layout:
//   msg[(b,k,h,n,d)] -> out[b, n', c], n' = (k*16+h)*4 + d/8, c = (d%8)*256 + n
__global__ __launch_bounds__(256) void attn_kernel(
    const float* __restrict__ qb, const float* __restrict__ kb,
    const float* __restrict__ vb, const float* __restrict__ attn_bias,
    const int* __restrict__ mask, const float* __restrict__ dist,
    const float* __restrict__ dist_bar, float* __restrict__ msg)
{
    extern __shared__ float sm[];
    float* Ks = sm;                  // 256*33
    float* Vs = Ks + 256 * 33;       // 256*33
    float* Ps = Vs + 256 * 33;       // 8 warps * 256*4
    float* Qs = Ps + 8 * 1024;       // 8 warps * 32

    int bh = blockIdx.x;
    int b = bh >> 4;
    int h = bh & 15;
    int tid = threadIdx.x;
    int lane = tid & 31;
    int warp = tid >> 5;

    float bar[4];
#pragma unroll
    for (int k = 0; k < 4; k++) bar[k] = dist_bar[k];

    // load K,V tiles for this (b,h)
    for (int idx = tid; idx < 256 * 32; idx += 256) {
        int m = idx >> 5;
        int d = idx & 31;
        Ks[m * 33 + d] = kb[(size_t)(b * 256 + m) * 512 + h * 32 + d];
        Vs[m * 33 + d] = vb[(size_t)(b * 256 + m) * 512 + h * 32 + d];
    }
    __syncthreads();

    float* Pw = Ps + warp * 1024;
    float* Qw = Qs + warp * 32;
    const float scl = 0.17677669529663687f; // 1/sqrt(32)

    for (int n = warp; n < 256; n += 8) {
        Qw[lane] = qb[(size_t)(b * 256 + n) * 512 + h * 32 + lane];
        __syncwarp();

        // scores: lane owns keys m = lane + 32*j
        float s[8];
#pragma unroll
        for (int j = 0; j < 8; j++) s[j] = 0.f;
#pragma unroll
        for (int d = 0; d < 32; d++) {
            float qv = Qw[d];
#pragma unroll
            for (int j = 0; j < 8; j++) s[j] += qv * Ks[(lane + 32 * j) * 33 + d];
        }

        unsigned pmbits = 0;
        float nd[8];
#pragma unroll
        for (int j = 0; j < 8; j++) {
            int m = lane + 32 * j;
            s[j] *= scl;
            if (mask[(size_t)(b * 256 + n) * 256 + m] != 0) pmbits |= (1u << j);
            nd[j] = (n == 0 || m == 0) ? 0.f
                                       : dist[(size_t)(b * 255 + (n - 1)) * 255 + (m - 1)];
        }

#pragma unroll
        for (int k = 0; k < 4; k++) {
            float sc[8];
            float mx = -3.4e38f;
#pragma unroll
            for (int j = 0; j < 8; j++) {
                int m = lane + 32 * j;
                float bv = attn_bias[(size_t)((b * 4 + k) * 256 + n) * 256 + m];
                bool within = (nd[j] < bar[k]) || (n == 0) || (m == 0);
                bool ok = ((pmbits >> j) & 1u) && within;
                sc[j] = ok ? (s[j] + bv) : -1e12f;
                mx = fmaxf(mx, sc[j]);
            }
#pragma unroll
            for (int o = 16; o > 0; o >>= 1)
                mx = fmaxf(mx, __shfl_xor_sync(0xffffffffu, mx, o));
            float sum = 0.f;
#pragma unroll
            for (int j = 0; j < 8; j++) {
                sc[j] = __expf(sc[j] - mx);
                sum += sc[j];
            }
#pragma unroll
            for (int o = 16; o > 0; o >>= 1)
                sum += __shfl_xor_sync(0xffffffffu, sum, o);
            float inv = 1.f / sum;
#pragma unroll
            for (int j = 0; j < 8; j++)
                Pw[(lane + 32 * j) * 4 + k] = sc[j] * inv;
        }
        __syncwarp();

        // one V pass for all 4 scales; lane owns output dim d = lane
        float a0 = 0.f, a1 = 0.f, a2 = 0.f, a3 = 0.f;
#pragma unroll 4
        for (int m = 0; m < 256; m++) {
            float4 pv = *(const float4*)&Pw[m * 4];
            float v = Vs[m * 33 + lane];
            a0 += pv.x * v;
            a1 += pv.y * v;
            a2 += pv.z * v;
            a3 += pv.w * v;
        }

        // scatter into the torch-faithful reshape layout
        int d = lane;
        int c = (d & 7) * 256 + n;
        float av[4] = {a0, a1, a2, a3};
#pragma unroll
        for (int k = 0; k < 4; k++) {
            int npr = (k * 16 + h) * 4 + (d >> 3);
            msg[(size_t)(b * 256 + npr) * 2048 + c] = av[k];
        }
        __syncwarp();  // protect Pw/Qw before next iteration's overwrite
    }
}

// ------------------- fused residual + LayerNorm ----------------------------
// out[row] = LN(a[row] + r[row]) * g + be ; D = 512, 256 threads per row.
__global__ __launch_bounds__(256) void add_ln_kernel(
    const float* __restrict__ a, const float* __restrict__ r,
    const float* __restrict__ g, const float* __restrict__ be,
    float* __restrict__ out)
{
    int row = blockIdx.x;
    int tid = threadIdx.x;
    int lane = tid & 31;
    int warp = tid >> 5;

    const float* ar = a + (size_t)row * 512;
    const float* rr = r + (size_t)row * 512;
    float v0 = ar[tid] + rr[tid];
    float v1 = ar[tid + 256] + rr[tid + 256];

    __shared__ float red[8];
    __shared__ float sMean, sRstd;

    float s = v0 + v1;
#pragma unroll
    for (int o = 16; o > 0; o >>= 1) s += __shfl_xor_sync(0xffffffffu, s, o);
    if (lane == 0) red[warp] = s;
    __syncthreads();
    if (tid == 0) {
        float t = 0.f;
#pragma unroll
        for (int i = 0; i < 8; i++) t += red[i];
        sMean = t * (1.f / 512.f);
    }
    __syncthreads();
    float mean = sMean;
    float d0 = v0 - mean;
    float d1 = v1 - mean;
    float q = d0 * d0 + d1 * d1;
#pragma unroll
    for (int o = 16; o > 0; o >>= 1) q += __shfl_xor_sync(0xffffffffu, q, o);
    if (lane == 0) red[warp] = q;
    __syncthreads();
    if (tid == 0) {
        float t = 0.f;
#pragma unroll
        for (int i = 0; i < 8; i++) t += red[i];
        sRstd = rsqrtf(t * (1.f / 512.f) + 1e-6f);
    }
    __syncthreads();
    float rstd = sRstd;
    out[(size_t)row * 512 + tid] = d0 * rstd * g[tid] + be[tid];
    out[(size_t)row * 512 + tid + 256] = d1 * rstd * g[tid + 256] + be[tid + 256];
}

// ------------------- launch ------------------------------------------------
extern "C" void kernel_launch(void* const* d_in, const int* in_sizes, int n_in,
                              void* d_out, int out_size)
{
    // inputs: x, dist, dist_bar, attn_bias, mask, [num_heads], Wq,bq,...,g2,be2
    int base = (n_in >= 24) ? 6 : 5;

    const float* x         = (const float*)d_in[0];
    const float* dist      = (const float*)d_in[1];
    const float* dist_bar  = (const float*)d_in[2];
    const float* attn_bias = (const float*)d_in[3];
    const int*   mask      = (const int*)d_in[4];
    const float* Wq  = (const float*)d_in[base + 0];
    const float* bq  = (const float*)d_in[base + 1];
    const float* Wk  = (const float*)d_in[base + 2];
    const float* bk  = (const float*)d_in[base + 3];
    const float* Wv  = (const float*)d_in[base + 4];
    const float* bv  = (const float*)d_in[base + 5];
    const float* W1  = (const float*)d_in[base + 6];
    const float* b1  = (const float*)d_in[base + 7];
    const float* W2  = (const float*)d_in[base + 8];
    const float* b2  = (const float*)d_in[base + 9];
    const float* g1  = (const float*)d_in[base + 10];
    const float* be1 = (const float*)d_in[base + 11];
    const float* Wf1 = (const float*)d_in[base + 12];
    const float* bf1 = (const float*)d_in[base + 13];
    const float* Wf2 = (const float*)d_in[base + 14];
    const float* bf2 = (const float*)d_in[base + 15];
    const float* g2  = (const float*)d_in[base + 16];
    const float* be2 = (const float*)d_in[base + 17];
    float* out = (float*)d_out;

    float *qb, *kb, *vb, *msgb, *t1, *t2, *yb, *t3, *t4;
    cudaGetSymbolAddress((void**)&qb, g_q);
    cudaGetSymbolAddress((void**)&kb, g_k);
    cudaGetSymbolAddress((void**)&vb, g_v);
    cudaGetSymbolAddress((void**)&msgb, g_msg);
    cudaGetSymbolAddress((void**)&t1, g_t1);
    cudaGetSymbolAddress((void**)&t2, g_t2);
    cudaGetSymbolAddress((void**)&yb, g_y);
    cudaGetSymbolAddress((void**)&t3, g_t3);
    cudaGetSymbolAddress((void**)&t4, g_t4);

    const int ATTN_SMEM = (256 * 33 * 2 + 8 * 1024 + 8 * 32) * 4; // 101376 B
    cudaFuncSetAttribute(attn_kernel,
                         cudaFuncAttributeMaxDynamicSharedMemorySize, ATTN_SMEM);

    dim3 blk(256);
    dim3 gD(D_ / 64, BN_ / 128);     // Nc=512
    dim3 gF(FFN_ / 64, BN_ / 128);   // Nc=2048

    // QKV projections
    gemm_kernel<0><<<gD, blk>>>(x, Wq, bq, qb, BN_, D_, D_);
    gemm_kernel<0><<<gD, blk>>>(x, Wk, bk, kb, BN_, D_, D_);
    gemm_kernel<0><<<gD, blk>>>(x, Wv, bv, vb, BN_, D_, D_);

    // fused multi-scale attention + torch-reshape scatter
    attn_kernel<<<B_ * H_, blk, ATTN_SMEM>>>(qb, kb, vb, attn_bias, mask,
                                             dist, dist_bar, msgb);

    // MLP: silu(msg @ W1 + b1) @ W2 + b2 ; y = LN(h + x)
    gemm_kernel<1><<<gD, blk>>>(msgb, W1, b1, t1, BN_, D_, KD_);
    gemm_kernel<0><<<gD, blk>>>(t1, W2, b2, t2, BN_, D_, D_);
    add_ln_kernel<<<BN_, blk>>>(t2, x, g1, be1, yb);

    // FFN: gelu(y @ Wf1 + bf1) @ Wf2 + bf2 ; out = LN(f + y)
    gemm_kernel<2><<<gF, blk>>>(yb, Wf1, bf1, t3, BN_, FFN_, D_);
    gemm_kernel<0><<<gD, blk>>>(t3, Wf2, bf2, t4, BN_, D_, FFN_);
    add_ln_kernel<<<BN_, blk>>>(t4, yb, g2, be2, out);
}

// round 4
// speedup vs baseline: 1.3503x; 1.3503x over previous
#include <cuda_runtime.h>
#include <math.h>

#define B_ 8
#define N_ 256
#define D_ 512
#define H_ 16
#define K_ 4
#define DK_ 32
#define FFN_ 2048
#define BN_ 2048   // B*N
#define KD_ 2048   // K*D

// ------------------- scratch (static device allocations) -------------------
__device__ float g_q[BN_ * D_];
__device__ float g_k[BN_ * D_];
__device__ float g_v[BN_ * D_];
__device__ float g_msg[BN_ * KD_];
__device__ float g_t1[BN_ * D_];
__device__ float g_t2[BN_ * D_];
__device__ float g_y[BN_ * D_];
__device__ float g_t3[BN_ * FFN_];
__device__ float g_t4[BN_ * D_];

// ------------------- fp32 tiled GEMM body: C = act(A@W + bias) -------------
// A [M, Kc] row-major, W [Kc, Nc] row-major, C [M, Nc].
// Block tile 128(M) x 64(N) x 16(K). 256 threads, 8x4 micro-tile.
// A tile stored k-major in smem so the inner loop is 3x LDS.128 + 32 FMA.
// Register prefetch of the next k-tile hides LDG latency under the FMAs.
template <int ACT>
__device__ __forceinline__ void gemm_body(
    const float* __restrict__ A, const float* __restrict__ W,
    const float* __restrict__ bias, float* __restrict__ C,
    int Nc, int Kc)
{
    __shared__ float As[16][132];   // [k][row], pitch 132 -> 2-way STS conflict max
    __shared__ float Bs[16][64];    // [k][col]

    int tid = threadIdx.x;
    int tx = tid & 15;
    int ty = tid >> 4;
    int rowBase = blockIdx.y * 128;
    int colBase = blockIdx.x * 64;

    int ar  = tid >> 2;          // 0..63 (second half at ar+64)
    int ac4 = (tid & 3) * 4;     // k-offset within tile: 0,4,8,12
    int br  = tid >> 4;          // 0..15
    int bc  = (tid & 15) * 4;

    const float* Ap0 = A + (size_t)(rowBase + ar) * Kc + ac4;
    const float* Ap1 = Ap0 + (size_t)64 * Kc;
    const float* Wp  = W + (size_t)br * Nc + colBase + bc;

    float4 pa0 = *(const float4*)Ap0;
    float4 pa1 = *(const float4*)Ap1;
    float4 pb  = *(const float4*)Wp;

    float acc[8][4];
#pragma unroll
    for (int i = 0; i < 8; i++)
#pragma unroll
        for (int j = 0; j < 4; j++) acc[i][j] = 0.f;

    for (int k0 = 0; k0 < Kc; k0 += 16) {
        // store prefetched tile (A transposed to k-major)
        As[ac4 + 0][ar] = pa0.x; As[ac4 + 1][ar] = pa0.y;
        As[ac4 + 2][ar] = pa0.z; As[ac4 + 3][ar] = pa0.w;
        As[ac4 + 0][ar + 64] = pa1.x; As[ac4 + 1][ar + 64] = pa1.y;
        As[ac4 + 2][ar + 64] = pa1.z; As[ac4 + 3][ar + 64] = pa1.w;
        *(float4*)&Bs[br][bc] = pb;
        __syncthreads();

        if (k0 + 16 < Kc) {   // prefetch next tile
            pa0 = *(const float4*)(Ap0 + k0 + 16);
            pa1 = *(const float4*)(Ap1 + k0 + 16);
            pb  = *(const float4*)(Wp + (size_t)(k0 + 16) * Nc);
        }

#pragma unroll
        for (int kk = 0; kk < 16; kk++) {
            float4 b4  = *(const float4*)&Bs[kk][tx * 4];
            float4 a40 = *(const float4*)&As[kk][ty * 8];
            float4 a41 = *(const float4*)&As[kk][ty * 8 + 4];
            float a[8] = {a40.x, a40.y, a40.z, a40.w, a41.x, a41.y, a41.z, a41.w};
#pragma unroll
            for (int i = 0; i < 8; i++) {
                acc[i][0] += a[i] * b4.x;
                acc[i][1] += a[i] * b4.y;
                acc[i][2] += a[i] * b4.z;
                acc[i][3] += a[i] * b4.w;
            }
        }
        __syncthreads();
    }

    float4 bi = *(const float4*)&bias[colBase + tx * 4];
    float bv[4] = {bi.x, bi.y, bi.z, bi.w};
#pragma unroll
    for (int i = 0; i < 8; i++) {
        int r = rowBase + ty * 8 + i;
        float o[4];
#pragma unroll
        for (int j = 0; j < 4; j++) {
            float v = acc[i][j] + bv[j];
            if (ACT == 1) {                       // SiLU
                v = v / (1.f + __expf(-v));
            } else if (ACT == 2) {                // exact GELU
                v = 0.5f * v * (1.f + erff(v * 0.70710678118654752f));
            }
            o[j] = v;
        }
        *(float4*)&C[(size_t)r * Nc + colBase + tx * 4] =
            make_float4(o[0], o[1], o[2], o[3]);
    }
}

template <int ACT>
__global__ __launch_bounds__(256) void gemm_kernel(
    const float* __restrict__ A, const float* __restrict__ W,
    const float* __restrict__ bias, float* __restrict__ C,
    int Nc, int Kc)
{
    gemm_body<ACT>(A, W, bias, C, Nc, Kc);
}

// fused Q/K/V projection: blockIdx.z picks the weight/out triple
__global__ __launch_bounds__(256) void qkv_kernel(
    const float* __restrict__ x,
    const float* __restrict__ Wq, const float* __restrict__ bq,
    const float* __restrict__ Wk, const float* __restrict__ bk,
    const float* __restrict__ Wv, const float* __restrict__ bv,
    float* __restrict__ q, float* __restrict__ k, float* __restrict__ v)
{
    int z = blockIdx.z;
    const float* W  = (z == 0) ? Wq : ((z == 1) ? Wk : Wv);
    const float* bb = (z == 0) ? bq : ((z == 1) ? bk : bv);
    float* C        = (z == 0) ? q  : ((z == 1) ? k  : v);
    gemm_body<0>(x, W, bb, C, D_, D_);
}

// ------------------- fused multi-scale attention ---------------------------
// grid (B*H, 4): block = one (b,h) and a 64-query chunk. 101KB smem -> 2 CTAs/SM.
// Each warp owns one query at a time; all 4 distance scales softmaxed, p stored
// float4-per-key, one V pass accumulates all 4 scales. Output scattered directly
// into the faithful torch-reshape layout:
//   msg[(b,k,h,n,d)] -> out[b, n', c], n' = (k*16+h)*4 + d/8, c = (d%8)*256 + n
__global__ __launch_bounds__(256, 2) void attn_kernel(
    const float* __restrict__ qb, const float* __restrict__ kb,
    const float* __restrict__ vb, const float* __restrict__ attn_bias,
    const int* __restrict__ mask, const float* __restrict__ dist,
    const float* __restrict__ dist_bar, float* __restrict__ msg)
{
    extern __shared__ float sm[];
    float* Ks = sm;                  // 256*33
    float* Vs = Ks + 256 * 33;       // 256*33
    float* Ps = Vs + 256 * 33;       // 8 warps * 256*4
    float* Qs = Ps + 8 * 1024;       // 8 warps * 32

    int bh = blockIdx.x;
    int b = bh >> 4;
    int h = bh & 15;
    int qbase = blockIdx.y * 64;
    int tid = threadIdx.x;
    int lane = tid & 31;
    int warp = tid >> 5;

    float bar[4];
#pragma unroll
    for (int k = 0; k < 4; k++) bar[k] = dist_bar[k];

    // load K,V tiles for this (b,h) (float4 global reads, conflict-free STS)
    for (int idx = tid; idx < 256 * 8; idx += 256) {
        int m = idx >> 3;
        int dq = (idx & 7) * 4;
        size_t gi = (size_t)(b * 256 + m) * 512 + h * 32 + dq;
        float4 k4 = *(const float4*)&kb[gi];
        float4 v4 = *(const float4*)&vb[gi];
        Ks[m * 33 + dq + 0] = k4.x; Ks[m * 33 + dq + 1] = k4.y;
        Ks[m * 33 + dq + 2] = k4.z; Ks[m * 33 + dq + 3] = k4.w;
        Vs[m * 33 + dq + 0] = v4.x; Vs[m * 33 + dq + 1] = v4.y;
        Vs[m * 33 + dq + 2] = v4.z; Vs[m * 33 + dq + 3] = v4.w;
    }
    __syncthreads();

    float* Pw = Ps + warp * 1024;
    float* Qw = Qs + warp * 32;
    const float scl = 0.17677669529663687f; // 1/sqrt(32)

    for (int n = qbase + warp; n < qbase + 64; n += 8) {
        Qw[lane] = qb[(size_t)(b * 256 + n) * 512 + h * 32 + lane];
        __syncwarp();

        // batched predicate/bias loads (max MLP, all LDGs issued up front)
        unsigned pmbits = 0;
        float nd[8];
        float bias_r[4][8];
        {
            const float* bp = attn_bias + ((size_t)(b * 4) * 256 + n) * 256 + lane;
#pragma unroll
            for (int j = 0; j < 8; j++) {
                int m = lane + 32 * j;
                if (mask[(size_t)(b * 256 + n) * 256 + m] != 0) pmbits |= (1u << j);
                nd[j] = (n == 0 || m == 0) ? 0.f
                                           : dist[(size_t)(b * 255 + (n - 1)) * 255 + (m - 1)];
#pragma unroll
                for (int k = 0; k < 4; k++)
                    bias_r[k][j] = bp[(size_t)k * 65536 + 32 * j];
            }
        }

        // scores: lane owns keys m = lane + 32*j
        float s[8];
#pragma unroll
        for (int j = 0; j < 8; j++) s[j] = 0.f;
#pragma unroll
        for (int d = 0; d < 32; d++) {
            float qv = Qw[d];
#pragma unroll
            for (int j = 0; j < 8; j++) s[j] += qv * Ks[(lane + 32 * j) * 33 + d];
        }
#pragma unroll
        for (int j = 0; j < 8; j++) s[j] *= scl;

#pragma unroll
        for (int k = 0; k < 4; k++) {
            float sc[8];
            float mx = -3.4e38f;
#pragma unroll
            for (int j = 0; j < 8; j++) {
                int m = lane + 32 * j;
                bool within = (nd[j] < bar[k]) || (n == 0) || (m == 0);
                bool ok = ((pmbits >> j) & 1u) && within;
                sc[j] = ok ? (s[j] + bias_r[k][j]) : -1e12f;
                mx = fmaxf(mx, sc[j]);
            }
#pragma unroll
            for (int o = 16; o > 0; o >>= 1)
                mx = fmaxf(mx, __shfl_xor_sync(0xffffffffu, mx, o));
            float sum = 0.f;
#pragma unroll
            for (int j = 0; j < 8; j++) {
                sc[j] = __expf(sc[j] - mx);
                sum += sc[j];
            }
#pragma unroll
            for (int o = 16; o > 0; o >>= 1)
                sum += __shfl_xor_sync(0xffffffffu, sum, o);
            float inv = 1.f / sum;
#pragma unroll
            for (int j = 0; j < 8; j++)
                Pw[(lane + 32 * j) * 4 + k] = sc[j] * inv;
        }
        __syncwarp();

        // one V pass for all 4 scales; lane owns output dim d = lane
        float a0 = 0.f, a1 = 0.f, a2 = 0.f, a3 = 0.f;
        const float* pw = Pw;
        const float* vp = Vs + lane;
#pragma unroll 8
        for (int m = 0; m < 256; m++) {
            float4 pv = *(const float4*)pw;
            float v = *vp;
            a0 += pv.x * v;
            a1 += pv.y * v;
            a2 += pv.z * v;
            a3 += pv.w * v;
            pw += 4;
            vp += 33;
        }

        // scatter into the torch-faithful reshape layout
        int d = lane;
        int c = (d & 7) * 256 + n;
        float av[4] = {a0, a1, a2, a3};
#pragma unroll
        for (int k = 0; k < 4; k++) {
            int npr = (k * 16 + h) * 4 + (d >> 3);
            msg[(size_t)(b * 256 + npr) * 2048 + c] = av[k];
        }
        __syncwarp();  // protect Pw/Qw before next iteration's overwrite
    }
}

// ------------------- fused residual + LayerNorm ----------------------------
__global__ __launch_bounds__(256) void add_ln_kernel(
    const float* __restrict__ a, const float* __restrict__ r,
    const float* __restrict__ g, const float* __restrict__ be,
    float* __restrict__ out)
{
    int row = blockIdx.x;
    int tid = threadIdx.x;
    int lane = tid & 31;
    int warp = tid >> 5;

    const float* ar = a + (size_t)row * 512;
    const float* rr = r + (size_t)row * 512;
    float v0 = ar[tid] + rr[tid];
    float v1 = ar[tid + 256] + rr[tid + 256];

    __shared__ float red[8];
    __shared__ float sMean, sRstd;

    float s = v0 + v1;
#pragma unroll
    for (int o = 16; o > 0; o >>= 1) s += __shfl_xor_sync(0xffffffffu, s, o);
    if (lane == 0) red[warp] = s;
    __syncthreads();
    if (tid == 0) {
        float t = 0.f;
#pragma unroll
        for (int i = 0; i < 8; i++) t += red[i];
        sMean = t * (1.f / 512.f);
    }
    __syncthreads();
    float mean = sMean;
    float d0 = v0 - mean;
    float d1 = v1 - mean;
    float q = d0 * d0 + d1 * d1;
#pragma unroll
    for (int o = 16; o > 0; o >>= 1) q += __shfl_xor_sync(0xffffffffu, q, o);
    if (lane == 0) red[warp] = q;
    __syncthreads();
    if (tid == 0) {
        float t = 0.f;
#pragma unroll
        for (int i = 0; i < 8; i++) t += red[i];
        sRstd = rsqrtf(t * (1.f / 512.f) + 1e-6f);
    }
    __syncthreads();
    float rstd = sRstd;
    out[(size_t)row * 512 + tid] = d0 * rstd * g[tid] + be[tid];
    out[(size_t)row * 512 + tid + 256] = d1 * rstd * g[tid + 256] + be[tid + 256];
}

// ------------------- launch ------------------------------------------------
extern "C" void kernel_launch(void* const* d_in, const int* in_sizes, int n_in,
                              void* d_out, int out_size)
{
    int base = (n_in >= 24) ? 6 : 5;

    const float* x         = (const float*)d_in[0];
    const float* dist      = (const float*)d_in[1];
    const float* dist_bar  = (const float*)d_in[2];
    const float* attn_bias = (const float*)d_in[3];
    const int*   mask      = (const int*)d_in[4];
    const float* Wq  = (const float*)d_in[base + 0];
    const float* bq  = (const float*)d_in[base + 1];
    const float* Wk  = (const float*)d_in[base + 2];
    const float* bk  = (const float*)d_in[base + 3];
    const float* Wv  = (const float*)d_in[base + 4];
    const float* bv  = (const float*)d_in[base + 5];
    const float* W1  = (const float*)d_in[base + 6];
    const float* b1  = (const float*)d_in[base + 7];
    const float* W2  = (const float*)d_in[base + 8];
    const float* b2  = (const float*)d_in[base + 9];
    const float* g1  = (const float*)d_in[base + 10];
    const float* be1 = (const float*)d_in[base + 11];
    const float* Wf1 = (const float*)d_in[base + 12];
    const float* bf1 = (const float*)d_in[base + 13];
    const float* Wf2 = (const float*)d_in[base + 14];
    const float* bf2 = (const float*)d_in[base + 15];
    const float* g2  = (const float*)d_in[base + 16];
    const float* be2 = (const float*)d_in[base + 17];
    float* out = (float*)d_out;

    float *qb, *kb, *vb, *msgb, *t1, *t2, *yb, *t3, *t4;
    cudaGetSymbolAddress((void**)&qb, g_q);
    cudaGetSymbolAddress((void**)&kb, g_k);
    cudaGetSymbolAddress((void**)&vb, g_v);
    cudaGetSymbolAddress((void**)&msgb, g_msg);
    cudaGetSymbolAddress((void**)&t1, g_t1);
    cudaGetSymbolAddress((void**)&t2, g_t2);
    cudaGetSymbolAddress((void**)&yb, g_y);
    cudaGetSymbolAddress((void**)&t3, g_t3);
    cudaGetSymbolAddress((void**)&t4, g_t4);

    const int ATTN_SMEM = (256 * 33 * 2 + 8 * 1024 + 8 * 32) * 4; // 101376 B
    cudaFuncSetAttribute(attn_kernel,
                         cudaFuncAttributeMaxDynamicSharedMemorySize, ATTN_SMEM);

    dim3 blk(256);
    dim3 gQKV(D_ / 64, BN_ / 128, 3);
    dim3 gD(D_ / 64, BN_ / 128);     // Nc=512
    dim3 gF(FFN_ / 64, BN_ / 128);   // Nc=2048
    dim3 gAttn(B_ * H_, 4);          // (b,h) x 4 query-chunks -> 512 blocks

    // QKV projections (one launch, z picks W)
    qkv_kernel<<<gQKV, blk>>>(x, Wq, bq, Wk, bk, Wv, bv, qb, kb, vb);

    // fused multi-scale attention + torch-reshape scatter
    attn_kernel<<<gAttn, blk, ATTN_SMEM>>>(qb, kb, vb, attn_bias, mask,
                                           dist, dist_bar, msgb);

    // MLP: silu(msg @ W1 + b1) @ W2 + b2 ; y = LN(h + x)
    gemm_kernel<1><<<gD, blk>>>(msgb, W1, b1, t1, D_, KD_);
    gemm_kernel<0><<<gD, blk>>>(t1, W2, b2, t2, D_, D_);
    add_ln_kernel<<<BN_, blk>>>(t2, x, g1, be1, yb);

    // FFN: gelu(y @ Wf1 + bf1) @ Wf2 + bf2 ; out = LN(f + y)
    gemm_kernel<2><<<gF, blk>>>(yb, Wf1, bf1, t3, FFN_, D_);
    gemm_kernel<0><<<gD, blk>>>(t3, Wf2, bf2, t4, D_, FFN_);
    add_ln_kernel<<<BN_, blk>>>(t4, yb, g2, be2, out);
}

// round 7
// speedup vs baseline: 2.2458x; 1.6632x over previous
#include <cuda_runtime.h>
#include <cuda_bf16.h>
#include <math.h>
#include <stdint.h>

#define B_ 8
#define N_ 256
#define D_ 512
#define H_ 16
#define K_ 4
#define DK_ 32
#define FFN_ 2048
#define BN_ 2048   // B*N
#define KD_ 2048   // K*D

// ------------------- scratch (static device allocations) -------------------
__device__ __align__(256) float g_q[BN_ * D_];
__device__ __align__(256) float g_k[BN_ * D_];
__device__ __align__(256) float g_v[BN_ * D_];
__device__ __align__(256) float g_msg[BN_ * KD_];
__device__ __align__(256) float g_t1[BN_ * D_];
__device__ __align__(256) float g_t2[BN_ * D_];
__device__ __align__(256) float g_y[BN_ * D_];
__device__ __align__(256) float g_t3[BN_ * FFN_];
__device__ __align__(256) float g_t4[BN_ * D_];

// ------------------- helpers ----------------------------------------------
__device__ __forceinline__ uint32_t smem_u32(const void* p) {
    uint32_t a;
    asm("{ .reg .u64 t; cvta.to.shared.u64 t, %1; cvt.u32.u64 %0, t; }"
        : "=r"(a) : "l"(p));
    return a;
}

__device__ __forceinline__ void ldsm_x4(uint32_t& r0, uint32_t& r1,
                                        uint32_t& r2, uint32_t& r3, uint32_t a) {
    asm volatile("ldmatrix.sync.aligned.m8n8.x4.shared.b16 {%0,%1,%2,%3}, [%4];"
                 : "=r"(r0), "=r"(r1), "=r"(r2), "=r"(r3) : "r"(a));
}
__device__ __forceinline__ void ldsm_x4_t(uint32_t& r0, uint32_t& r1,
                                          uint32_t& r2, uint32_t& r3, uint32_t a) {
    asm volatile("ldmatrix.sync.aligned.m8n8.x4.trans.shared.b16 {%0,%1,%2,%3}, [%4];"
                 : "=r"(r0), "=r"(r1), "=r"(r2), "=r"(r3) : "r"(a));
}

__device__ __forceinline__ void mma_bf16(float* c, const uint32_t* a,
                                         const uint32_t* b) {
    asm volatile(
        "mma.sync.aligned.m16n8k16.row.col.f32.bf16.bf16.f32 "
        "{%0,%1,%2,%3}, {%4,%5,%6,%7}, {%8,%9}, {%0,%1,%2,%3};"
        : "+f"(c[0]), "+f"(c[1]), "+f"(c[2]), "+f"(c[3])
        : "r"(a[0]), "r"(a[1]), "r"(a[2]), "r"(a[3]), "r"(b[0]), "r"(b[1]));
}

// split a float into bf16 hi + bf16 lo; pack pairs (low element = low half)
__device__ __forceinline__ void split2(float x, float y, uint32_t& hi, uint32_t& lo) {
    __nv_bfloat16 hx = __float2bfloat16_rn(x);
    __nv_bfloat16 hy = __float2bfloat16_rn(y);
    __nv_bfloat16 lx = __float2bfloat16_rn(x - __bfloat162float(hx));
    __nv_bfloat16 ly = __float2bfloat16_rn(y - __bfloat162float(hy));
    __nv_bfloat162 h2 = __nv_bfloat162(hx, hy);
    __nv_bfloat162 l2 = __nv_bfloat162(lx, ly);
    hi = *(uint32_t*)&h2;
    lo = *(uint32_t*)&l2;
}

// ------------------- bf16x3 tensor-core GEMM body --------------------------
// C[M,Nc] = act(A[M,Kc] @ W[Kc,Nc] + bias). Tile 128(M) x 64(N), K-chunk 32.
// 3-term split: D += Ah*Bh + Ah*Bl + Al*Bh (bf16 mma, fp32 accum).
// 8 warps = 4(M) x 2(N); warp tile 32x32.
// A smem [m][k] pitch 40 bf16 (80B rows -> conflict-free LDSM).
// B smem [k][n] pitch 72 bf16 (144B rows), read via ldmatrix.x4.trans.
#define A_PITCH 40
#define B_PITCH 72

template <int ACT>
__device__ __forceinline__ void tc_gemm_body(
    const float* __restrict__ A, const float* __restrict__ W,
    const float* __restrict__ bias, float* __restrict__ C,
    int Nc, int Kc)
{
    __shared__ __align__(16) __nv_bfloat16 sAh[128 * A_PITCH];
    __shared__ __align__(16) __nv_bfloat16 sAl[128 * A_PITCH];
    __shared__ __align__(16) __nv_bfloat16 sBh[32 * B_PITCH];
    __shared__ __align__(16) __nv_bfloat16 sBl[32 * B_PITCH];

    int tid = threadIdx.x;
    int lane = tid & 31;
    int warp = tid >> 5;
    int warpM = warp & 3;        // 0..3 -> m offset 0,32,64,96
    int warpN = warp >> 2;       // 0..1 -> n offset 0,32
    int rowBase = blockIdx.y * 128;
    int colBase = blockIdx.x * 64;

    uint32_t uAh = smem_u32(sAh), uAl = smem_u32(sAl);
    uint32_t uBh = smem_u32(sBh), uBl = smem_u32(sBl);

    // global pointers for this thread's fill slice
    // A: 128x32 fp32 per chunk = 1024 float4; idx = tid + it*256
    int am = 0, ak = 0;
    {
        am = tid >> 3;              // base row for it=0 (rows advance by 32/it)
        ak = (tid & 7) * 4;
    }
    const float* Aptr = A + (size_t)(rowBase + am) * Kc + ak;   // + it*32 rows
    // B: 32x64 fp32 per chunk = 512 float4; idx = tid + it*256
    int bk = tid >> 4;              // k row (advance 16/it)
    int bn = (tid & 15) * 4;
    const float* Wptr = W + (size_t)bk * Nc + colBase + bn;

    float acc[2][4][4];
#pragma unroll
    for (int mt = 0; mt < 2; mt++)
#pragma unroll
        for (int nb = 0; nb < 4; nb++)
#pragma unroll
            for (int j = 0; j < 4; j++) acc[mt][nb][j] = 0.f;

    // prefetch chunk 0
    float4 pa[4], pb[2];
#pragma unroll
    for (int it = 0; it < 4; it++)
        pa[it] = *(const float4*)(Aptr + (size_t)(it * 32) * Kc);
#pragma unroll
    for (int it = 0; it < 2; it++)
        pb[it] = *(const float4*)(Wptr + (size_t)(it * 16) * Nc);

    // precomputed LDSM base addresses (byte offsets added per use)
    // A: row = warpM*32 + mt*16 + (lane&15); col bytes = ks*32 + (lane>>4)*16
    uint32_t aRow = (uint32_t)(warpM * 32 + (lane & 15)) * (A_PITCH * 2)
                    + ((lane >> 4) << 4);
    // B: row k = ks*16 + (lane&15); col bytes = (warpN*32 + nbp*16)*2 + (lane>>4)*16
    uint32_t bRow = (uint32_t)(lane & 15) * (B_PITCH * 2)
                    + (uint32_t)(warpN * 32) * 2 + ((lane >> 4) << 4);

    int nch = Kc >> 5;
    for (int c = 0; c < nch; c++) {
        // ---- store prefetched chunk to smem (split hi/lo) ----
#pragma unroll
        for (int it = 0; it < 4; it++) {
            int m = am + it * 32;
            uint32_t off = (uint32_t)(m * A_PITCH + ak) * 2;
            uint32_t h0, l0, h1, l1;
            split2(pa[it].x, pa[it].y, h0, l0);
            split2(pa[it].z, pa[it].w, h1, l1);
            *(uint2*)((char*)sAh + off) = make_uint2(h0, h1);
            *(uint2*)((char*)sAl + off) = make_uint2(l0, l1);
        }
#pragma unroll
        for (int it = 0; it < 2; it++) {
            int k = bk + it * 16;
            uint32_t off = (uint32_t)(k * B_PITCH + bn) * 2;
            uint32_t h0, l0, h1, l1;
            split2(pb[it].x, pb[it].y, h0, l0);
            split2(pb[it].z, pb[it].w, h1, l1);
            *(uint2*)((char*)sBh + off) = make_uint2(h0, h1);
            *(uint2*)((char*)sBl + off) = make_uint2(l0, l1);
        }
        __syncthreads();

        // ---- prefetch next chunk ----
        if (c + 1 < nch) {
            const float* An = Aptr + (c + 1) * 32;
            const float* Wn = Wptr + (size_t)((c + 1) * 32) * Nc;
#pragma unroll
            for (int it = 0; it < 4; it++)
                pa[it] = *(const float4*)(An + (size_t)(it * 32) * Kc);
#pragma unroll
            for (int it = 0; it < 2; it++)
                pb[it] = *(const float4*)(Wn + (size_t)(it * 16) * Nc);
        }

        // ---- MMA on this chunk: 2 k-steps of 16 ----
#pragma unroll
        for (int ks = 0; ks < 2; ks++) {
            uint32_t ah[2][4], al[2][4];
#pragma unroll
            for (int mt = 0; mt < 2; mt++) {
                uint32_t aoff = aRow + (uint32_t)(mt * 16) * (A_PITCH * 2) + ks * 32;
                ldsm_x4(ah[mt][0], ah[mt][1], ah[mt][2], ah[mt][3], uAh + aoff);
                ldsm_x4(al[mt][0], al[mt][1], al[mt][2], al[mt][3], uAl + aoff);
            }
            uint32_t bh[4][2], bl[4][2];
#pragma unroll
            for (int nbp = 0; nbp < 2; nbp++) {   // each x4 covers 2 n-tiles
                uint32_t boff = bRow + (uint32_t)(ks * 16) * (B_PITCH * 2)
                                + (uint32_t)(nbp * 16) * 2;
                ldsm_x4_t(bh[nbp * 2][0], bh[nbp * 2][1],
                          bh[nbp * 2 + 1][0], bh[nbp * 2 + 1][1], uBh + boff);
                ldsm_x4_t(bl[nbp * 2][0], bl[nbp * 2][1],
                          bl[nbp * 2 + 1][0], bl[nbp * 2 + 1][1], uBl + boff);
            }
#pragma unroll
            for (int mt = 0; mt < 2; mt++)
#pragma unroll
                for (int nb = 0; nb < 4; nb++) {
                    mma_bf16(acc[mt][nb], ah[mt], bh[nb]);
                    mma_bf16(acc[mt][nb], ah[mt], bl[nb]);
                    mma_bf16(acc[mt][nb], al[mt], bh[nb]);
                }
        }
        __syncthreads();
    }

    // ---- epilogue: bias + activation + float2 stores ----
#pragma unroll
    for (int mt = 0; mt < 2; mt++) {
        int r0 = rowBase + warpM * 32 + mt * 16 + (lane >> 2);
#pragma unroll
        for (int nb = 0; nb < 4; nb++) {
            int col = colBase + warpN * 32 + nb * 8 + (lane & 3) * 2;
            float b0 = bias[col], b1 = bias[col + 1];
#pragma unroll
            for (int half = 0; half < 2; half++) {
                int r = r0 + half * 8;
                float v0 = acc[mt][nb][half * 2 + 0] + b0;
                float v1 = acc[mt][nb][half * 2 + 1] + b1;
                if (ACT == 1) {                       // SiLU
                    v0 = v0 / (1.f + __expf(-v0));
                    v1 = v1 / (1.f + __expf(-v1));
                } else if (ACT == 2) {                // exact GELU
                    v0 = 0.5f * v0 * (1.f + erff(v0 * 0.70710678118654752f));
                    v1 = 0.5f * v1 * (1.f + erff(v1 * 0.70710678118654752f));
                }
                *(float2*)&C[(size_t)r * Nc + col] = make_float2(v0, v1);
            }
        }
    }
}

template <int ACT>
__global__ __launch_bounds__(256) void tc_gemm(
    const float* __restrict__ A, const float* __restrict__ W,
    const float* __restrict__ bias, float* __restrict__ C,
    int Nc, int Kc)
{
    tc_gemm_body<ACT>(A, W, bias, C, Nc, Kc);
}

// fused Q/K/V projection: blockIdx.z picks the weight/out triple
__global__ __launch_bounds__(256) void tc_qkv(
    const float* __restrict__ x,
    const float* __restrict__ Wq, const float* __restrict__ bq,
    const float* __restrict__ Wk, const float* __restrict__ bk,
    const float* __restrict__ Wv, const float* __restrict__ bv,
    float* __restrict__ q, float* __restrict__ k, float* __restrict__ v)
{
    int z = blockIdx.z;
    const float* W  = (z == 0) ? Wq : ((z == 1) ? Wk : Wv);
    const float* bb = (z == 0) ? bq : ((z == 1) ? bk : bv);
    float* C        = (z == 0) ? q  : ((z == 1) ? k  : v);
    tc_gemm_body<0>(x, W, bb, C, D_, D_);
}

// ------------------- fused multi-scale attention ---------------------------
// grid (B*H, 4): block = one (b,h) and a 64-query chunk. 101KB smem -> 2 CTAs/SM.
__global__ __launch_bounds__(256, 2) void attn_kernel(
    const float* __restrict__ qb, const float* __restrict__ kb,
    const float* __restrict__ vb, const float* __restrict__ attn_bias,
    const int* __restrict__ mask, const float* __restrict__ dist,
    const float* __restrict__ dist_bar, float* __restrict__ msg)
{
    extern __shared__ float sm[];
    float* Ks = sm;                  // 256*33
    float* Vs = Ks + 256 * 33;       // 256*33
    float* Ps = Vs + 256 * 33;       // 8 warps * 256*4
    float* Qs = Ps + 8 * 1024;       // 8 warps * 32

    int bh = blockIdx.x;
    int b = bh >> 4;
    int h = bh & 15;
    int qbase = blockIdx.y * 64;
    int tid = threadIdx.x;
    int lane = tid & 31;
    int warp = tid >> 5;

    float bar[4];
#pragma unroll
    for (int k = 0; k < 4; k++) bar[k] = dist_bar[k];

    for (int idx = tid; idx < 256 * 8; idx += 256) {
        int m = idx >> 3;
        int dq = (idx & 7) * 4;
        size_t gi = (size_t)(b * 256 + m) * 512 + h * 32 + dq;
        float4 k4 = *(const float4*)&kb[gi];
        float4 v4 = *(const float4*)&vb[gi];
        Ks[m * 33 + dq + 0] = k4.x; Ks[m * 33 + dq + 1] = k4.y;
        Ks[m * 33 + dq + 2] = k4.z; Ks[m * 33 + dq + 3] = k4.w;
        Vs[m * 33 + dq + 0] = v4.x; Vs[m * 33 + dq + 1] = v4.y;
        Vs[m * 33 + dq + 2] = v4.z; Vs[m * 33 + dq + 3] = v4.w;
    }
    __syncthreads();

    float* Pw = Ps + warp * 1024;
    float* Qw = Qs + warp * 32;
    const float scl = 0.17677669529663687f; // 1/sqrt(32)

    for (int n = qbase + warp; n < qbase + 64; n += 8) {
        Qw[lane] = qb[(size_t)(b * 256 + n) * 512 + h * 32 + lane];
        __syncwarp();

        unsigned pmbits = 0;
        float nd[8];
        float bias_r[4][8];
        {
            const float* bp = attn_bias + ((size_t)(b * 4) * 256 + n) * 256 + lane;
#pragma unroll
            for (int j = 0; j < 8; j++) {
                int m = lane + 32 * j;
                if (mask[(size_t)(b * 256 + n) * 256 + m] != 0) pmbits |= (1u << j);
                nd[j] = (n == 0 || m == 0) ? 0.f
                                           : dist[(size_t)(b * 255 + (n - 1)) * 255 + (m - 1)];
#pragma unroll
                for (int k = 0; k < 4; k++)
                    bias_r[k][j] = bp[(size_t)k * 65536 + 32 * j];
            }
        }

        float s[8];
#pragma unroll
        for (int j = 0; j < 8; j++) s[j] = 0.f;
#pragma unroll
        for (int d = 0; d < 32; d++) {
            float qv = Qw[d];
#pragma unroll
            for (int j = 0; j < 8; j++) s[j] += qv * Ks[(lane + 32 * j) * 33 + d];
        }
#pragma unroll
        for (int j = 0; j < 8; j++) s[j] *= scl;

#pragma unroll
        for (int k = 0; k < 4; k++) {
            float sc[8];
            float mx = -3.4e38f;
#pragma unroll
            for (int j = 0; j < 8; j++) {
                int m = lane + 32 * j;
                bool within = (nd[j] < bar[k]) || (n == 0) || (m == 0);
                bool ok = ((pmbits >> j) & 1u) && within;
                sc[j] = ok ? (s[j] + bias_r[k][j]) : -1e12f;
                mx = fmaxf(mx, sc[j]);
            }
#pragma unroll
            for (int o = 16; o > 0; o >>= 1)
                mx = fmaxf(mx, __shfl_xor_sync(0xffffffffu, mx, o));
            float sum = 0.f;
#pragma unroll
            for (int j = 0; j < 8; j++) {
                sc[j] = __expf(sc[j] - mx);
                sum += sc[j];
            }
#pragma unroll
            for (int o = 16; o > 0; o >>= 1)
                sum += __shfl_xor_sync(0xffffffffu, sum, o);
            float inv = 1.f / sum;
#pragma unroll
            for (int j = 0; j < 8; j++)
                Pw[(lane + 32 * j) * 4 + k] = sc[j] * inv;
        }
        __syncwarp();

        float a0 = 0.f, a1 = 0.f, a2 = 0.f, a3 = 0.f;
        const float* pw = Pw;
        const float* vp = Vs + lane;
#pragma unroll 8
        for (int m = 0; m < 256; m++) {
            float4 pv = *(const float4*)pw;
            float v = *vp;
            a0 += pv.x * v;
            a1 += pv.y * v;
            a2 += pv.z * v;
            a3 += pv.w * v;
            pw += 4;
            vp += 33;
        }

        int d = lane;
        int c = (d & 7) * 256 + n;
        float av[4] = {a0, a1, a2, a3};
#pragma unroll
        for (int k = 0; k < 4; k++) {
            int npr = (k * 16 + h) * 4 + (d >> 3);
            msg[(size_t)(b * 256 + npr) * 2048 + c] = av[k];
        }
        __syncwarp();
    }
}

// ------------------- fused residual + LayerNorm ----------------------------
__global__ __launch_bounds__(256) void add_ln_kernel(
    const float* __restrict__ a, const float* __restrict__ r,
    const float* __restrict__ g, const float* __restrict__ be,
    float* __restrict__ out)
{
    int row = blockIdx.x;
    int tid = threadIdx.x;
    int lane = tid & 31;
    int warp = tid >> 5;

    const float* ar = a + (size_t)row * 512;
    const float* rr = r + (size_t)row * 512;
    float v0 = ar[tid] + rr[tid];
    float v1 = ar[tid + 256] + rr[tid + 256];

    __shared__ float red[8];
    __shared__ float sMean, sRstd;

    float s = v0 + v1;
#pragma unroll
    for (int o = 16; o > 0; o >>= 1) s += __shfl_xor_sync(0xffffffffu, s, o);
    if (lane == 0) red[warp] = s;
    __syncthreads();
    if (tid == 0) {
        float t = 0.f;
#pragma unroll
        for (int i = 0; i < 8; i++) t += red[i];
        sMean = t * (1.f / 512.f);
    }
    __syncthreads();
    float mean = sMean;
    float d0 = v0 - mean;
    float d1 = v1 - mean;
    float q = d0 * d0 + d1 * d1;
#pragma unroll
    for (int o = 16; o > 0; o >>= 1) q += __shfl_xor_sync(0xffffffffu, q, o);
    if (lane == 0) red[warp] = q;
    __syncthreads();
    if (tid == 0) {
        float t = 0.f;
#pragma unroll
        for (int i = 0; i < 8; i++) t += red[i];
        sRstd = rsqrtf(t * (1.f / 512.f) + 1e-6f);
    }
    __syncthreads();
    float rstd = sRstd;
    out[(size_t)row * 512 + tid] = d0 * rstd * g[tid] + be[tid];
    out[(size_t)row * 512 + tid + 256] = d1 * rstd * g[tid + 256] + be[tid + 256];
}

// ------------------- launch ------------------------------------------------
extern "C" void kernel_launch(void* const* d_in, const int* in_sizes, int n_in,
                              void* d_out, int out_size)
{
    int base = (n_in >= 24) ? 6 : 5;

    const float* x         = (const float*)d_in[0];
    const float* dist      = (const float*)d_in[1];
    const float* dist_bar  = (const float*)d_in[2];
    const float* attn_bias = (const float*)d_in[3];
    const int*   mask      = (const int*)d_in[4];
    const float* Wq  = (const float*)d_in[base + 0];
    const float* bq  = (const float*)d_in[base + 1];
    const float* Wk  = (const float*)d_in[base + 2];
    const float* bk  = (const float*)d_in[base + 3];
    const float* Wv  = (const float*)d_in[base + 4];
    const float* bv  = (const float*)d_in[base + 5];
    const float* W1  = (const float*)d_in[base + 6];
    const float* b1  = (const float*)d_in[base + 7];
    const float* W2  = (const float*)d_in[base + 8];
    const float* b2  = (const float*)d_in[base + 9];
    const float* g1  = (const float*)d_in[base + 10];
    const float* be1 = (const float*)d_in[base + 11];
    const float* Wf1 = (const float*)d_in[base + 12];
    const float* bf1 = (const float*)d_in[base + 13];
    const float* Wf2 = (const float*)d_in[base + 14];
    const float* bf2 = (const float*)d_in[base + 15];
    const float* g2  = (const float*)d_in[base + 16];
    const float* be2 = (const float*)d_in[base + 17];
    float* out = (float*)d_out;

    float *qb, *kb, *vb, *msgb, *t1, *t2, *yb, *t3, *t4;
    cudaGetSymbolAddress((void**)&qb, g_q);
    cudaGetSymbolAddress((void**)&kb, g_k);
    cudaGetSymbolAddress((void**)&vb, g_v);
    cudaGetSymbolAddress((void**)&msgb, g_msg);
    cudaGetSymbolAddress((void**)&t1, g_t1);
    cudaGetSymbolAddress((void**)&t2, g_t2);
    cudaGetSymbolAddress((void**)&yb, g_y);
    cudaGetSymbolAddress((void**)&t3, g_t3);
    cudaGetSymbolAddress((void**)&t4, g_t4);

    const int ATTN_SMEM = (256 * 33 * 2 + 8 * 1024 + 8 * 32) * 4; // 101376 B
    cudaFuncSetAttribute(attn_kernel,
                         cudaFuncAttributeMaxDynamicSharedMemorySize, ATTN_SMEM);

    dim3 blk(256);
    dim3 gQKV(D_ / 64, BN_ / 128, 3);    // 8 x 16 x 3
    dim3 gD(D_ / 64, BN_ / 128);         // 8 x 16
    dim3 gF(FFN_ / 64, BN_ / 128);       // 32 x 16
    dim3 gAttn(B_ * H_, 4);              // 512 blocks

    // QKV projections (tensor cores, z picks W)
    tc_qkv<<<gQKV, blk>>>(x, Wq, bq, Wk, bk, Wv, bv, qb, kb, vb);

    // fused multi-scale attention + torch-reshape scatter
    attn_kernel<<<gAttn, blk, ATTN_SMEM>>>(qb, kb, vb, attn_bias, mask,
                                           dist, dist_bar, msgb);

    // MLP: silu(msg @ W1 + b1) @ W2 + b2 ; y = LN(h + x)
    tc_gemm<1><<<gD, blk>>>(msgb, W1, b1, t1, D_, KD_);
    tc_gemm<0><<<gD, blk>>>(t1, W2, b2, t2, D_, D_);
    add_ln_kernel<<<BN_, blk>>>(t2, x, g1, be1, yb);

    // FFN: gelu(y @ Wf1 + bf1) @ Wf2 + bf2 ; out = LN(f + y)
    tc_gemm<2><<<gF, blk>>>(yb, Wf1, bf1, t3, FFN_, D_);
    tc_gemm<0><<<gD, blk>>>(t3, Wf2, bf2, t4, D_, FFN_);
    add_ln_kernel<<<BN_, blk>>>(t4, yb, g2, be2, out);
}